// round 4
// baseline (speedup 1.0000x reference)
#include <cuda_runtime.h>
#include <cuda_bf16.h>
#include <cstdint>

// Problem constants
#define Bn   64
#define Cn   256
#define HWn  1024
#define B2n  128      // 2*B
// TEMPERATURE = 0.5  -> logits = 2 * sim

// ---------------- scratch (static __device__, no allocation) ----------------
__device__ __align__(16) __nv_bfloat16 g_feats[(size_t)HWn * B2n * Cn]; // 64MB: [pixel][b'][c]
__device__ double g_acc;

// ---------------- helpers ----------------
__device__ __forceinline__ uint32_t smem_u32(const void* p) {
    uint32_t a;
    asm("{ .reg .u64 t; cvta.to.shared.u64 t, %1; cvt.u32.u64 %0, t; }" : "=r"(a) : "l"(p));
    return a;
}

__device__ __forceinline__ void ldmatrix_x4(uint32_t* r, uint32_t addr) {
    asm volatile("ldmatrix.sync.aligned.m8n8.x4.shared.b16 {%0,%1,%2,%3}, [%4];"
                 : "=r"(r[0]), "=r"(r[1]), "=r"(r[2]), "=r"(r[3]) : "r"(addr));
}
__device__ __forceinline__ void ldmatrix_x2(uint32_t* r, uint32_t addr) {
    asm volatile("ldmatrix.sync.aligned.m8n8.x2.shared.b16 {%0,%1}, [%2];"
                 : "=r"(r[0]), "=r"(r[1]) : "r"(addr));
}
__device__ __forceinline__ void mma_bf16(float* d, const uint32_t* a, const uint32_t* b) {
    asm volatile(
        "mma.sync.aligned.m16n8k16.row.col.f32.bf16.bf16.f32 "
        "{%0,%1,%2,%3}, {%4,%5,%6,%7}, {%8,%9}, {%0,%1,%2,%3};"
        : "+f"(d[0]), "+f"(d[1]), "+f"(d[2]), "+f"(d[3])
        : "r"(a[0]), "r"(a[1]), "r"(a[2]), "r"(a[3]), "r"(b[0]), "r"(b[1]));
}

// ================= Pass 1: normalize + transpose to g_feats =================
// grid (HW/32, 2B), block 256. Block = one b' (0..127), 32 consecutive hw.
__global__ void __launch_bounds__(256)
norm_transpose_kernel(const float* __restrict__ x, const float* __restrict__ y) {
    __shared__ float sm[32][Cn + 1];   // [hw_local][c]
    const int tid  = threadIdx.x;
    const int lane = tid & 31;
    const int wrp  = tid >> 5;         // 0..7
    const int b2   = blockIdx.y;       // 0..127
    const int hw0  = blockIdx.x * 32;

    const float* src = (b2 < Bn) ? x : y;
    const int b = b2 & (Bn - 1);
    const float* base = src + ((size_t)b * Cn) * HWn + hw0;

    #pragma unroll
    for (int k = 0; k < Cn / 8; k++) {
        int c = wrp + k * 8;
        sm[lane][c] = base[(size_t)c * HWn + lane];
    }
    __syncthreads();

    const float eps = 1.1920929e-07f;  // finfo(float32).eps
    #pragma unroll
    for (int p = 0; p < 4; p++) {
        int hw = p * 8 + wrp;          // warp owns one hw per pass
        float v[8];
        float ss = 0.f;
        #pragma unroll
        for (int k = 0; k < 8; k++) {
            v[k] = sm[hw][lane + 32 * k];
            ss += v[k] * v[k];
        }
        #pragma unroll
        for (int o = 16; o > 0; o >>= 1) ss += __shfl_xor_sync(0xffffffffu, ss, o);
        float scale = 1.0f / fmaxf(sqrtf(ss), eps);
        __nv_bfloat16* out = g_feats + ((size_t)(hw0 + hw) * B2n + b2) * Cn;
        #pragma unroll
        for (int k = 0; k < 8; k++)
            out[lane + 32 * k] = __float2bfloat16(v[k] * scale);
    }
}

// ================= Pass 2: per-pixel 128x128x256 bf16 HMMA + log-softmax ====
// grid 1024, block 256 (8 warps). Warp tile 64x32: 4 m-blocks x 4 n-blocks.
#define PITCH_B   528                       // 264 bf16 per row (256 data + 8 pad)
#define TILE_SZ   (128 * PITCH_B)           // 67584 B

__global__ void __launch_bounds__(256, 2)
pixel_kernel() {
    extern __shared__ __align__(16) char smem[];
    __shared__ float rs[128][4];
    __shared__ float pv[128];
    __shared__ float red[4];

    const int tid  = threadIdx.x;
    const int lane = tid & 31;
    const int w    = tid >> 5;          // 0..7
    const int mblk = (w & 1) * 64;      // row block
    const int nblk = (w >> 1) * 32;     // col block

    // ---- stage tile: 128 rows x 256 bf16 (512B data), row pitch 528 B ----
    // 128 rows x 32 chunks(16B) = 4096 chunks; 256 threads x 16 iters.
    {
        const uint4* src = reinterpret_cast<const uint4*>(
            g_feats + (size_t)blockIdx.x * B2n * Cn);
        #pragma unroll
        for (int j = 0; j < 16; j++) {
            int idx = tid + j * 256;            // 16B chunk id, 0..4095
            int r   = idx >> 5;                 // row 0..127
            int ch  = idx & 31;                 // chunk within row
            *reinterpret_cast<uint4*>(smem + r * PITCH_B + ch * 16) = src[idx];
        }
    }
    __syncthreads();

    const uint32_t base = smem_u32(smem);
    // per-lane ldmatrix address components
    const uint32_t a_off = (uint32_t)(lane & 15) * PITCH_B + ((lane >> 4) & 1) * 16;
    const uint32_t b_off = (uint32_t)(lane & 7)  * PITCH_B + ((lane >> 3) & 1) * 16;

    float acc[4][4][4];
    #pragma unroll
    for (int mt = 0; mt < 4; mt++)
        #pragma unroll
        for (int nt = 0; nt < 4; nt++)
            #pragma unroll
            for (int e = 0; e < 4; e++) acc[mt][nt][e] = 0.f;

    #pragma unroll
    for (int ks = 0; ks < 16; ks++) {
        const uint32_t kb = (uint32_t)ks * 32;   // 16 bf16 = 32 bytes
        uint32_t a[4][4];
        #pragma unroll
        for (int mt = 0; mt < 4; mt++)
            ldmatrix_x4(a[mt], base + (uint32_t)(mblk + mt * 16) * PITCH_B + a_off + kb);
        #pragma unroll
        for (int nt = 0; nt < 4; nt++) {
            uint32_t b[2];
            ldmatrix_x2(b, base + (uint32_t)(nblk + nt * 8) * PITCH_B + b_off + kb);
            #pragma unroll
            for (int mt = 0; mt < 4; mt++)
                mma_bf16(acc[mt][nt], a[mt], b);
        }
    }

    // ---- epilogue in registers: logits = 2*sim; skip diag; grab partner ----
    const int qrow = lane >> 2;          // 0..7
    const int qcol = (lane & 3) * 2;
    float psum[4][2];
    #pragma unroll
    for (int mt = 0; mt < 4; mt++) { psum[mt][0] = 0.f; psum[mt][1] = 0.f; }

    #pragma unroll
    for (int mt = 0; mt < 4; mt++)
        #pragma unroll
        for (int nt = 0; nt < 4; nt++)
            #pragma unroll
            for (int e = 0; e < 4; e++) {
                int row = mblk + mt * 16 + qrow + ((e >> 1) * 8);
                int col = nblk + nt * 8 + qcol + (e & 1);
                float v = 2.0f * acc[mt][nt][e];
                if (col != row) psum[mt][e >> 1] += __expf(v);
                if (col == (row ^ 64)) pv[row] = v;
            }

    // quad reduce (lanes sharing a row differ only in lane&3)
    #pragma unroll
    for (int mt = 0; mt < 4; mt++)
        #pragma unroll
        for (int h = 0; h < 2; h++) {
            float s = psum[mt][h];
            s += __shfl_xor_sync(0xffffffffu, s, 1);
            s += __shfl_xor_sync(0xffffffffu, s, 2);
            psum[mt][h] = s;
        }
    if ((lane & 3) == 0) {
        #pragma unroll
        for (int mt = 0; mt < 4; mt++)
            #pragma unroll
            for (int h = 0; h < 2; h++)
                rs[mblk + mt * 16 + qrow + 8 * h][nblk >> 5] = psum[mt][h];
    }
    __syncthreads();

    if (tid < 128) {
        float s = rs[tid][0] + rs[tid][1] + rs[tid][2] + rs[tid][3];
        float loss = pv[tid] - __logf(s);
        #pragma unroll
        for (int o = 16; o > 0; o >>= 1) loss += __shfl_xor_sync(0xffffffffu, loss, o);
        if (lane == 0) red[tid >> 5] = loss;
    }
    __syncthreads();
    if (tid == 0)
        atomicAdd(&g_acc, (double)(red[0] + red[1] + red[2] + red[3]));
}

// ================= tiny init / finish kernels =================
__global__ void init_kernel() { g_acc = 0.0; }
__global__ void finish_kernel(float* out) {
    out[0] = (float)(-g_acc / (double)((size_t)HWn * B2n));
}

// ================= launch =================
extern "C" void kernel_launch(void* const* d_in, const int* in_sizes, int n_in,
                              void* d_out, int out_size) {
    (void)in_sizes; (void)n_in; (void)out_size;
    cudaFuncSetAttribute(pixel_kernel, cudaFuncAttributeMaxDynamicSharedMemorySize, TILE_SZ);

    init_kernel<<<1, 1>>>();
    dim3 g1(HWn / 32, B2n);
    norm_transpose_kernel<<<g1, 256>>>((const float*)d_in[0], (const float*)d_in[1]);
    pixel_kernel<<<HWn, 256, TILE_SZ>>>();
    finish_kernel<<<1, 1>>>((float*)d_out);
}